// round 15
// baseline (speedup 1.0000x reference)
#include <cuda_runtime.h>
#include <cstdint>

#define DIN   1024
#define NH    16
#define NK    8
#define TSEQ  2048

// Scratch (device globals — no allocation in kernel_launch).
__device__ float g_scores[4 * TSEQ * NK];          // [token][k]
__device__ float g_wr[NH * NK * 64 * 64];          // tf32-rounded weights

__device__ __forceinline__ float tf32_rna(float f) {
    uint32_t u;
    asm("cvt.rna.tf32.f32 %0, %1;" : "=r"(u) : "f"(f));
    return __uint_as_float(u);
}

// ---------------------------------------------------------------------------
// Kernel 1: round W to tf32 (unbiased, round-to-nearest) into g_wr.
// ---------------------------------------------------------------------------
__global__ void roundw_kernel(const float* __restrict__ w) {
    int i = (blockIdx.x * blockDim.x + threadIdx.x) * 4;
    float4 v = *reinterpret_cast<const float4*>(w + i);
    v.x = tf32_rna(v.x); v.y = tf32_rna(v.y);
    v.z = tf32_rna(v.z); v.w = tf32_rna(v.w);
    *reinterpret_cast<float4*>(g_wr + i) = v;
}

// ---------------------------------------------------------------------------
// Kernel 2: scores[t,k] = phi[t%2048,k] + dot(x[t,:], diag[k,:])
// One block per token; 256 threads = 8 warps, warp w handles k=w.
// ---------------------------------------------------------------------------
__global__ void scores_kernel(const float* __restrict__ x,
                              const float* __restrict__ diag,
                              const float* __restrict__ phi) {
    __shared__ __align__(16) float sx[DIN];
    const int t   = blockIdx.x;
    const int tid = threadIdx.x;
    *reinterpret_cast<float4*>(sx + tid * 4) =
        *reinterpret_cast<const float4*>(x + (size_t)t * DIN + tid * 4);
    __syncthreads();
    const int w = tid >> 5, lane = tid & 31;
    const float* dr = diag + w * DIN;
    float sum = 0.f;
#pragma unroll 8
    for (int j = 0; j < 32; ++j)
        sum = fmaf(sx[lane + 32 * j], __ldg(dr + lane + 32 * j), sum);
#pragma unroll
    for (int o = 16; o; o >>= 1) sum += __shfl_xor_sync(0xffffffffu, sum, o);
    if (lane == 0)
        g_scores[(size_t)t * NK + w] = phi[(t & (TSEQ - 1)) * NK + w] + sum;
}

// ---------------------------------------------------------------------------
// Kernel 3: main GEMM. out[t, h*64+o] = sum_k s[t,k] * (x_h[t,:] @ W[h,k])[o]
// CTA tile: 64 tokens x 64 outputs (one head). 4 warps, each 32x32.
// A (x head-slice, tf32) held in registers across all 8 k-iterations.
// W[h,k] double-buffered via cp.async. Per-k mma partials scaled by s in fp32.
// ---------------------------------------------------------------------------
__device__ __forceinline__ void cp_async16(uint32_t saddr, const void* g) {
    asm volatile("cp.async.cg.shared.global [%0], [%1], 16;" :: "r"(saddr), "l"(g));
}
__device__ __forceinline__ void cp_commit() {
    asm volatile("cp.async.commit_group;");
}

__device__ __forceinline__ void mma_tf32(float c[4], const uint32_t a[4], const uint32_t b[2]) {
    asm volatile(
        "mma.sync.aligned.m16n8k8.row.col.f32.tf32.tf32.f32 "
        "{%0,%1,%2,%3}, {%4,%5,%6,%7}, {%8,%9}, {%0,%1,%2,%3};"
        : "+f"(c[0]), "+f"(c[1]), "+f"(c[2]), "+f"(c[3])
        : "r"(a[0]), "r"(a[1]), "r"(a[2]), "r"(a[3]), "r"(b[0]), "r"(b[1]));
}

constexpr int SWS = 72;  // smem row stride (floats). 72%32==8 -> B-fragment LDS conflict-free.

__global__ void __launch_bounds__(128) main_kernel(const float* __restrict__ x,
                                                   float* __restrict__ out) {
    __shared__ __align__(16) float sbuf[2][64 * SWS];   // W double-buffer / x staging
    __shared__ __align__(16) float ss[64 * NK];         // scores tile

    const int t0   = blockIdx.x * 64;
    const int h    = blockIdx.y;
    const int tid  = threadIdx.x;
    const int warp = tid >> 5, lane = tid & 31;
    const int wm = warp >> 1, wn = warp & 1;       // 2x2 warp grid
    const int group = lane >> 2, tg = lane & 3;

    const float* wbase = g_wr + (size_t)h * NK * 4096;

    // Prefetch W[k=0] -> sbuf[0]
    {
        const float* ws = wbase;
#pragma unroll
        for (int it = 0; it < 8; ++it) {
            int e4 = it * 128 + tid;
            int row = e4 >> 4, c = (e4 & 15) << 2;
            cp_async16((uint32_t)__cvta_generic_to_shared(&sbuf[0][row * SWS + c]),
                       ws + e4 * 4);
        }
        cp_commit();
    }

    // Stage x head-slice (tf32-rounded) -> sbuf[1]. FULL tile: 1024 float4s.
#pragma unroll
    for (int it = 0; it < 8; ++it) {
        int e4 = it * 128 + tid;          // 0..1023 float4s of the 64x64 tile
        int row = e4 >> 4, c = (e4 & 15) << 2;
        float4 v = *reinterpret_cast<const float4*>(
            x + (size_t)(t0 + row) * DIN + h * 64 + c);
        v.x = tf32_rna(v.x); v.y = tf32_rna(v.y);
        v.z = tf32_rna(v.z); v.w = tf32_rna(v.w);
        *reinterpret_cast<float4*>(&sbuf[1][row * SWS + c]) = v;
    }
    // Stage scores tile (64 tokens x 8 k)
    *reinterpret_cast<float4*>(&ss[tid * 4]) =
        *reinterpret_cast<const float4*>(g_scores + (size_t)t0 * NK + tid * 4);
    __syncthreads();

    // A fragments in registers for the whole i-range (8 k-steps of 8), both m-atoms.
    uint32_t a[8][2][4];
#pragma unroll
    for (int s8 = 0; s8 < 8; ++s8)
#pragma unroll
        for (int ma = 0; ma < 2; ++ma) {
            int r0 = wm * 32 + ma * 16 + group;
            int cc = s8 * 8 + tg;
            a[s8][ma][0] = __float_as_uint(sbuf[1][r0 * SWS + cc]);
            a[s8][ma][1] = __float_as_uint(sbuf[1][(r0 + 8) * SWS + cc]);
            a[s8][ma][2] = __float_as_uint(sbuf[1][r0 * SWS + cc + 4]);
            a[s8][ma][3] = __float_as_uint(sbuf[1][(r0 + 8) * SWS + cc + 4]);
        }
    __syncthreads();   // all warps done reading sbuf[1]

    // Prefetch W[k=1] -> sbuf[1]
    {
        const float* ws = wbase + 4096;
#pragma unroll
        for (int it = 0; it < 8; ++it) {
            int e4 = it * 128 + tid;
            int row = e4 >> 4, c = (e4 & 15) << 2;
            cp_async16((uint32_t)__cvta_generic_to_shared(&sbuf[1][row * SWS + c]),
                       ws + e4 * 4);
        }
        cp_commit();
    }

    float acc[2][4][4];
#pragma unroll
    for (int i = 0; i < 2; ++i)
#pragma unroll
        for (int j = 0; j < 4; ++j)
#pragma unroll
            for (int r = 0; r < 4; ++r) acc[i][j][r] = 0.f;

#pragma unroll
    for (int k = 0; k < NK; ++k) {
        if (k == NK - 1) asm volatile("cp.async.wait_group 0;");
        else             asm volatile("cp.async.wait_group 1;");
        __syncthreads();
        const float* swp = sbuf[k & 1];

        float sv[2][2];
#pragma unroll
        for (int ma = 0; ma < 2; ++ma) {
            int r0 = wm * 32 + ma * 16 + group;
            sv[ma][0] = ss[r0 * NK + k];
            sv[ma][1] = ss[(r0 + 8) * NK + k];
        }

        float ck[2][4][4];
#pragma unroll
        for (int i = 0; i < 2; ++i)
#pragma unroll
            for (int j = 0; j < 4; ++j)
#pragma unroll
                for (int r = 0; r < 4; ++r) ck[i][j][r] = 0.f;

#pragma unroll
        for (int s8 = 0; s8 < 8; ++s8) {
            uint32_t b[4][2];
#pragma unroll
            for (int na = 0; na < 4; ++na) {
                int col = wn * 32 + na * 8 + group;
                b[na][0] = __float_as_uint(swp[(s8 * 8 + tg) * SWS + col]);
                b[na][1] = __float_as_uint(swp[(s8 * 8 + 4 + tg) * SWS + col]);
            }
#pragma unroll
            for (int ma = 0; ma < 2; ++ma)
#pragma unroll
                for (int na = 0; na < 4; ++na)
                    mma_tf32(ck[ma][na], a[s8][ma], b[na]);
        }

        // acc += s[t,k] * ck  (fp32, exact)
#pragma unroll
        for (int ma = 0; ma < 2; ++ma)
#pragma unroll
            for (int na = 0; na < 4; ++na) {
                acc[ma][na][0] = fmaf(sv[ma][0], ck[ma][na][0], acc[ma][na][0]);
                acc[ma][na][1] = fmaf(sv[ma][0], ck[ma][na][1], acc[ma][na][1]);
                acc[ma][na][2] = fmaf(sv[ma][1], ck[ma][na][2], acc[ma][na][2]);
                acc[ma][na][3] = fmaf(sv[ma][1], ck[ma][na][3], acc[ma][na][3]);
            }

        __syncthreads();   // done reading sbuf[k&1]
        if (k + 2 < NK) {  // prefetch W[k+2] into the buffer just freed
            const float* ws = wbase + (size_t)(k + 2) * 4096;
            float* dst = sbuf[k & 1];
#pragma unroll
            for (int it = 0; it < 8; ++it) {
                int e4 = it * 128 + tid;
                int row = e4 >> 4, c = (e4 & 15) << 2;
                cp_async16((uint32_t)__cvta_generic_to_shared(&dst[row * SWS + c]),
                           ws + e4 * 4);
            }
            cp_commit();
        }
    }

    // Epilogue: float2 stores, fully covering the tile.
#pragma unroll
    for (int ma = 0; ma < 2; ++ma) {
        int r0 = t0 + wm * 32 + ma * 16 + group;
#pragma unroll
        for (int na = 0; na < 4; ++na) {
            int col = h * 64 + wn * 32 + na * 8 + 2 * tg;
            float2 v0 = make_float2(acc[ma][na][0], acc[ma][na][1]);
            float2 v1 = make_float2(acc[ma][na][2], acc[ma][na][3]);
            *reinterpret_cast<float2*>(out + (size_t)r0 * DIN + col) = v0;
            *reinterpret_cast<float2*>(out + (size_t)(r0 + 8) * DIN + col) = v1;
        }
    }
}

// ---------------------------------------------------------------------------
// Launch. Inputs (metadata order): x, weight, diag, phi. Output fp32.
// ---------------------------------------------------------------------------
extern "C" void kernel_launch(void* const* d_in, const int* in_sizes, int n_in,
                              void* d_out, int out_size) {
    const float* x    = (const float*)d_in[0];
    const float* w    = (const float*)d_in[1];
    const float* diag = (const float*)d_in[2];
    const float* phi  = (const float*)d_in[3];
    float* out = (float*)d_out;

    const int tokens = in_sizes[0] / DIN;          // B*T (8192 for B=4)

    roundw_kernel<<<(NH * NK * 64 * 64) / (256 * 4), 256>>>(w);
    scores_kernel<<<tokens, 256>>>(x, diag, phi);
    dim3 grid(tokens / 64, NH);
    main_kernel<<<grid, 128>>>(x, out);
}